// round 13
// baseline (speedup 1.0000x reference)
#include <cuda_runtime.h>
#include <math.h>

#define NB 8
#define NC 3

// ---------------- scratch (device globals; no runtime allocation) ----------------
__device__ float g_x [NB*NC*256*256];   // UNSCALED sample conv output (no sigma, no bias)
__device__ float g_h0[NB*NC*512*512];
__device__ float g_h1[NB*NC*256*256];
__device__ float g_h2[NB*NC*128*128];
__device__ float g_h3[NB*NC*64*64];
__device__ float g_p1[NB*NC*128*128];
__device__ float g_p2[NB*NC*64*64];
__device__ float g_inv_sigma;
__device__ unsigned int g_counts[8];    // zero-init at load; reset by mega finalize
__device__ unsigned int g_esti16;
__device__ unsigned int g_done = 0;
__device__ unsigned int g_bar_cnt = 0;
__device__ unsigned int g_bar_sense = 0;

// ---------------- fused: sample conv (4x4 s4, unscaled) + ctx stage 0 ----------------
__global__ void k_fused(const float* __restrict__ x,
                        const float* __restrict__ samw,
                        const float* __restrict__ cw,
                        const float* __restrict__ cb,
                        const float* __restrict__ bng,
                        const float* __restrict__ bnb) {
    __shared__ float ssw[144];
    __shared__ float scw[81], scb[3], sinv[3], sbb[3];
    int tid = threadIdx.x;
    if (tid < 144) ssw[tid] = samw[tid];
    if (tid < 81)  scw[tid] = cw[tid];
    if (tid < 3) {
        scb[tid]  = cb[tid];
        sinv[tid] = bng[tid] * rsqrtf(1.001f);
        sbb[tid]  = bnb[tid];
    }
    __syncthreads();

    int ox = threadIdx.x;
    int oy = blockIdx.x;
    int b  = blockIdx.y;

    float as0 = 0.f, as1 = 0.f, as2 = 0.f;
    float ac[2][2][3];
    #pragma unroll
    for (int sy = 0; sy < 2; sy++)
        #pragma unroll
        for (int sx = 0; sx < 2; sx++)
            #pragma unroll
            for (int oc = 0; oc < 3; oc++)
                ac[sy][sx][oc] = scb[oc];

    bool left = (ox > 0);

    #pragma unroll
    for (int ic = 0; ic < 3; ic++) {
        const float* base = x + (size_t)(b*3 + ic)*1024*1024;
        float inv = sinv[ic], bb = sbb[ic];
        #pragma unroll
        for (int r5 = 0; r5 < 5; r5++) {
            int iy = 4*oy + r5 - 1;
            float u0, u1, u2, u3, u4;
            if (iy >= 0) {
                const float* rp = base + (size_t)iy*1024 + 4*ox;
                float4 v4 = *reinterpret_cast<const float4*>(rp);
                float vm = left ? rp[-1] : 0.f;
                u0 = left ? fmaxf(fmaf(inv, vm, bb), 0.f) : 0.f;
                u1 = fmaxf(fmaf(inv, v4.x, bb), 0.f);
                u2 = fmaxf(fmaf(inv, v4.y, bb), 0.f);
                u3 = fmaxf(fmaf(inv, v4.z, bb), 0.f);
                u4 = fmaxf(fmaf(inv, v4.w, bb), 0.f);
                if (r5 >= 1) {
                    int ky = r5 - 1;
                    const float* w0 = &ssw[(0*3 + ic)*16 + ky*4];
                    const float* w1 = &ssw[(1*3 + ic)*16 + ky*4];
                    const float* w2 = &ssw[(2*3 + ic)*16 + ky*4];
                    as0 += w0[0]*v4.x + w0[1]*v4.y + w0[2]*v4.z + w0[3]*v4.w;
                    as1 += w1[0]*v4.x + w1[1]*v4.y + w1[2]*v4.z + w1[3]*v4.w;
                    as2 += w2[0]*v4.x + w2[1]*v4.y + w2[2]*v4.z + w2[3]*v4.w;
                }
            } else {
                u0 = u1 = u2 = u3 = u4 = 0.f;
            }
            if (r5 <= 2) {
                #pragma unroll
                for (int oc = 0; oc < 3; oc++) {
                    const float* wp = &scw[oc*27 + ic*9 + r5*3];
                    ac[0][0][oc] = fmaf(wp[0], u0, fmaf(wp[1], u1, fmaf(wp[2], u2, ac[0][0][oc])));
                    ac[0][1][oc] = fmaf(wp[0], u2, fmaf(wp[1], u3, fmaf(wp[2], u4, ac[0][1][oc])));
                }
            }
            if (r5 >= 2) {
                int ky = r5 - 2;
                #pragma unroll
                for (int oc = 0; oc < 3; oc++) {
                    const float* wp = &scw[oc*27 + ic*9 + ky*3];
                    ac[1][0][oc] = fmaf(wp[0], u0, fmaf(wp[1], u1, fmaf(wp[2], u2, ac[1][0][oc])));
                    ac[1][1][oc] = fmaf(wp[0], u2, fmaf(wp[1], u3, fmaf(wp[2], u4, ac[1][1][oc])));
                }
            }
        }
    }

    g_x[((b*3 + 0)*256 + oy)*256 + ox] = as0;
    g_x[((b*3 + 1)*256 + oy)*256 + ox] = as1;
    g_x[((b*3 + 2)*256 + oy)*256 + ox] = as2;

    #pragma unroll
    for (int oc = 0; oc < 3; oc++) {
        #pragma unroll
        for (int sy = 0; sy < 2; sy++) {
            size_t o = ((size_t)(b*3 + oc)*512 + 2*oy + sy)*512 + 2*ox;
            *reinterpret_cast<float2*>(g_h0 + o) = make_float2(ac[sy][0][oc], ac[sy][1][oc]);
        }
    }
}

// ---------------- per-pixel ctx conv body (stages 1..3) ----------------
template<int STAGE>
__device__ __forceinline__ void ctx_px_body(int i,
                                            const float* sw, const float* sb,
                                            const float* sinv, const float* sbb) {
    constexpr int INH  = (STAGE == 1) ? 512 : (STAGE == 2) ? 256 : 128;
    constexpr int OUTW = INH / 2;
    constexpr int LOG  = (STAGE == 1) ? 8 : (STAGE == 2) ? 7 : 6;
    const float* in = (STAGE == 1) ? g_h0 : (STAGE == 2) ? g_h1 : g_h2;
    float* outp     = (STAGE == 1) ? g_h1 : (STAGE == 2) ? g_h2 : g_h3;

    int ox = i & (OUTW - 1);
    int oy = (i >> LOG) & (OUTW - 1);
    int b  = i >> (2*LOG);

    float a0 = sb[0], a1 = sb[1], a2 = sb[2];
    bool left = (ox > 0);
    #pragma unroll
    for (int ic = 0; ic < 3; ic++) {
        const float* base = in + (size_t)(b*3 + ic)*INH*INH;
        float inv = sinv[ic], bb = sbb[ic];
        #pragma unroll
        for (int r = 0; r < 3; r++) {
            int iy = 2*oy + r - 1;
            float uL = 0.f, u0 = 0.f, u1 = 0.f;
            if (iy >= 0) {
                const float* rp = base + (size_t)iy*INH + 2*ox;
                float2 v = *reinterpret_cast<const float2*>(rp);
                u0 = fmaxf(fmaf(inv, v.x, bb), 0.f);
                u1 = fmaxf(fmaf(inv, v.y, bb), 0.f);
                if (left) uL = fmaxf(fmaf(inv, rp[-1], bb), 0.f);
            }
            const float* wp = &sw[ic*9 + r*3];
            a0 = fmaf(wp[0],  uL, fmaf(wp[1],  u0, fmaf(wp[2],  u1, a0)));
            a1 = fmaf(wp[27], uL, fmaf(wp[28], u0, fmaf(wp[29], u1, a1)));
            a2 = fmaf(wp[54], uL, fmaf(wp[55], u0, fmaf(wp[56], u1, a2)));
        }
    }
    outp[((b*3 + 0)*OUTW + oy)*OUTW + ox] = a0;
    outp[((b*3 + 1)*OUTW + oy)*OUTW + ox] = a1;
    outp[((b*3 + 2)*OUTW + oy)*OUTW + ox] = a2;
}

// ---------------- role-split: ctx1 (blocks [0,2048)) + pools (blocks [2048,2176)) ----------------
__global__ void k_ctx1pool(const float* __restrict__ w1c, const float* __restrict__ b1c,
                           const float* __restrict__ bng1, const float* __restrict__ bnb1,
                           const float* __restrict__ samw, const float* __restrict__ samb,
                           const float* __restrict__ pw1, const float* __restrict__ pb1,
                           const float* __restrict__ pw2, const float* __restrict__ pb2) {
    int tid = threadIdx.x;
    if (blockIdx.x < 2048) {
        __shared__ float sw[81], sb[3], sinv[3], sbb[3];
        for (int t = tid; t < 81; t += 256) sw[t] = w1c[t];
        if (tid < 3) {
            sb[tid]   = b1c[tid];
            sinv[tid] = bng1[tid] * rsqrtf(1.001f);
            sbb[tid]  = bnb1[tid];
        }
        __syncthreads();
        int i = blockIdx.x*256 + tid;
        ctx_px_body<1>(i, sw, sb, sinv, sbb);
    } else {
        __shared__ float sG[9];
        __shared__ float sis;
        __shared__ float sw1[36], sw2[36], sb1[3], sb2[3], sbs[3];
        if (tid < 36) { sw1[tid] = pw1[tid]; sw2[tid] = pw2[tid]; }
        if (tid >= 64 && tid < 67) {
            int c = tid - 64;
            sb1[c] = pb1[c]; sb2[c] = pb2[c]; sbs[c] = samb[c];
        }
        if (tid >= 96 && tid < 105) {
            int t9 = tid - 96;
            int ii = t9 / 3, jj = t9 % 3;
            float s0 = 0.f, s1 = 0.f, s2 = 0.f, s3 = 0.f;
            #pragma unroll
            for (int k = 0; k < 48; k += 4) {
                s0 += samw[ii*48 + k + 0] * samw[jj*48 + k + 0];
                s1 += samw[ii*48 + k + 1] * samw[jj*48 + k + 1];
                s2 += samw[ii*48 + k + 2] * samw[jj*48 + k + 2];
                s3 += samw[ii*48 + k + 3] * samw[jj*48 + k + 3];
            }
            sG[t9] = (s0 + s1) + (s2 + s3);
        }
        __syncthreads();
        if (tid == 0) {
            float g00 = sG[0], g01 = sG[1], g02 = sG[2];
            float g11 = sG[4], g12 = sG[5], g22 = sG[8];
            float q  = (g00 + g11 + g22) * (1.f/3.f);
            float pp = g01*g01 + g02*g02 + g12*g12;
            float d0 = g00 - q, d1 = g11 - q, d2 = g22 - q;
            float p2 = d0*d0 + d1*d1 + d2*d2 + 2.f*pp;
            float lam;
            if (p2 <= 1e-30f) {
                lam = q;
            } else {
                float p  = sqrtf(p2 * (1.f/6.f));
                float ip = 1.f/p;
                float b00 = d0*ip, b11 = d1*ip, b22 = d2*ip;
                float b01 = g01*ip, b02 = g02*ip, b12 = g12*ip;
                float detB = b00*(b11*b22 - b12*b12)
                           - b01*(b01*b22 - b12*b02)
                           + b02*(b01*b12 - b11*b02);
                float r = fminf(1.f, fmaxf(-1.f, 0.5f*detB));
                lam = q + 2.f*p*cosf(acosf(r)*(1.f/3.f));
            }
            float is = rsqrtf(lam);
            sis = is;
            if (blockIdx.x == 2048) g_inv_sigma = is;
        }
        __syncthreads();
        float is = sis;

        int i  = (blockIdx.x - 2048)*256 + tid;
        int ox = i & 63;
        int oy = (i >> 6) & 63;
        int b  = i >> 12;

        float p1v[2][2][3];
        #pragma unroll
        for (int sy = 0; sy < 2; sy++)
            #pragma unroll
            for (int sx = 0; sx < 2; sx++)
                #pragma unroll
                for (int mc = 0; mc < 3; mc++)
                    p1v[sy][sx][mc] = sb1[mc];

        #pragma unroll
        for (int ic = 0; ic < 3; ic++) {
            const float* base = g_x + (size_t)(b*3 + ic)*65536 + (size_t)(4*oy)*256 + 4*ox;
            float bsc = sbs[ic];
            float rx[4][4];
            #pragma unroll
            for (int r = 0; r < 4; r++) {
                float4 v = *reinterpret_cast<const float4*>(base + r*256);
                rx[r][0] = fmaf(v.x, is, bsc);
                rx[r][1] = fmaf(v.y, is, bsc);
                rx[r][2] = fmaf(v.z, is, bsc);
                rx[r][3] = fmaf(v.w, is, bsc);
            }
            #pragma unroll
            for (int mc = 0; mc < 3; mc++) {
                const float* wp = &sw1[mc*12 + ic*4];
                #pragma unroll
                for (int sy = 0; sy < 2; sy++)
                    #pragma unroll
                    for (int sx = 0; sx < 2; sx++)
                        p1v[sy][sx][mc] += wp[0]*rx[2*sy][2*sx]   + wp[1]*rx[2*sy][2*sx+1]
                                         + wp[2]*rx[2*sy+1][2*sx] + wp[3]*rx[2*sy+1][2*sx+1];
            }
        }

        #pragma unroll
        for (int mc = 0; mc < 3; mc++)
            #pragma unroll
            for (int sy = 0; sy < 2; sy++) {
                size_t o = ((size_t)(b*3 + mc)*128 + 2*oy + sy)*128 + 2*ox;
                *reinterpret_cast<float2*>(g_p1 + o) = make_float2(p1v[sy][0][mc], p1v[sy][1][mc]);
            }

        #pragma unroll
        for (int oc = 0; oc < 3; oc++) {
            float a = sb2[oc];
            #pragma unroll
            for (int mc = 0; mc < 3; mc++) {
                const float* wp = &sw2[oc*12 + mc*4];
                a += wp[0]*p1v[0][0][mc] + wp[1]*p1v[0][1][mc]
                   + wp[2]*p1v[1][0][mc] + wp[3]*p1v[1][1][mc];
            }
            g_p2[((size_t)(b*3 + oc)*64 + oy)*64 + ox] = a;
        }
    }
}

// ---------------- ctx2 + ctx3 in one kernel with a co-resident grid barrier ----------------
__global__ void __launch_bounds__(256, 4)
k_tail23(const float* __restrict__ w2c, const float* __restrict__ b2c,
         const float* __restrict__ bng2, const float* __restrict__ bnb2,
         const float* __restrict__ w3c, const float* __restrict__ b3c,
         const float* __restrict__ bng3, const float* __restrict__ bnb3) {
    __shared__ float sw2[81], sb2[3], sinv2[3], sbb2[3];
    __shared__ float sw3[81], sb3[3], sinv3[3], sbb3[3];
    int tid = threadIdx.x;
    for (int t = tid; t < 81; t += 256) { sw2[t] = w2c[t]; sw3[t] = w3c[t]; }
    if (tid < 3) {
        sb2[tid]   = b2c[tid];
        sinv2[tid] = bng2[tid] * rsqrtf(1.001f);
        sbb2[tid]  = bnb2[tid];
        sb3[tid]   = b3c[tid];
        sinv3[tid] = bng3[tid] * rsqrtf(1.001f);
        sbb3[tid]  = bnb3[tid];
    }
    __syncthreads();

    int i = blockIdx.x*256 + tid;
    ctx_px_body<2>(i, sw2, sb2, sinv2, sbb2);

    __threadfence();
    __syncthreads();
    if (tid == 0) {
        unsigned int S = *(volatile unsigned int*)&g_bar_sense;
        unsigned int a = atomicAdd(&g_bar_cnt, 1u);
        if (a == gridDim.x - 1u) {
            g_bar_cnt = 0u;
            __threadfence();
            atomicExch(&g_bar_sense, S ^ 1u);
        } else {
            while (*(volatile unsigned int*)&g_bar_sense == S) { }
        }
    }
    __syncthreads();

    if (i < NB*64*64) {
        ctx_px_body<3>(i, sw3, sb3, sinv3, sbb3);
    }
}

// ---------------- soft VQ of one scalar (no side effects; returns argmin) ----------------
__device__ __forceinline__ float vq8(float x, const float* sc, int& imin) {
    float dd[8];
    float dmin = 3.4e38f;
    imin = 0;
    #pragma unroll
    for (int k = 0; k < 8; k++) {
        float d = (x - sc[k])*(x - sc[k]);
        dd[k] = d;
        if (d < dmin) { dmin = d; imin = k; }
    }
    float s = 0.f, sn = 0.f;
    #pragma unroll
    for (int k = 0; k < 8; k++) {
        float e = __expf(dmin - dd[k]);
        s += e;
        sn = fmaf(e, sc[k], sn);
    }
    return __fdividef(sn, s);
}

// ---------------- mega: one thread per HALF-res cell -> 2x2 pixel block ----------------
// Conditions constant per half cell; c2 value shared by the whole quarter cell
// (4 threads recompute it; only the quadrant leader contributes count + units).
// Histogram counts packed as 4-bit nibbles in one register (max 4 per bin per
// thread), reduced warp-wide -> no per-vq8 atomics. esti units (1/16): c2 quarter
// cell=16 (leader), c1 half=16, c0 half=64.
__global__ void k_mega(const float* __restrict__ thresh,
                       const float* __restrict__ centers,
                       const float* __restrict__ samb,
                       float* __restrict__ out, int soft_n) {
    __shared__ float sc[8];
    __shared__ unsigned int shist[8];
    __shared__ unsigned int sesti;
    __shared__ float sth[2];
    __shared__ float sbs[3];
    __shared__ float s_is;
    int tid = threadIdx.x;
    if (tid < 8) { sc[tid] = centers[tid]; shist[tid] = 0u; }
    if (tid < 2) sth[tid] = thresh[tid];
    if (tid < 3) sbs[tid] = samb[tid];
    if (tid == 0) { sesti = 0u; s_is = g_inv_sigma; }
    __syncthreads();

    int t = blockIdx.x*256 + tid;          // half-cell index, 0..393215 (grid exact: 1536)
    int hx = t & 127, hy = (t >> 7) & 127, bc = t >> 14;
    int qi = bc*4096 + (hy >> 1)*64 + (hx >> 1);
    int pbase = bc*65536 + (hy*2)*256 + hx*2;

    unsigned int units;
    unsigned int hcnt = 0u;

    float f2 = 0.5f*(tanhf(g_h3[qi]) + 1.0f);
    if (f2 < sth[1]) {
        // c2: quarter cell shares xq = p2[qi]; only quadrant leader counts
        int imin;
        float v = vq8(g_p2[qi], sc, imin);
        bool leader = ((hx & 1) == 0) && ((hy & 1) == 0);
        if (leader) { hcnt += 1u << (imin*4); units = 16u; }
        else units = 0u;
        float2 vv = make_float2(v, v);
        *reinterpret_cast<float2*>(out + pbase)       = vv;
        *reinterpret_cast<float2*>(out + pbase + 256) = vv;
    } else {
        float f1 = 0.5f*(tanhf(g_h2[t]) + 1.0f);
        if (f1 < sth[0]) {
            // c1: half cell shares xq = p1[t]
            int imin;
            float v = vq8(g_p1[t], sc, imin);
            hcnt += 1u << (imin*4);
            units = 16u;
            float2 vv = make_float2(v, v);
            *reinterpret_cast<float2*>(out + pbase)       = vv;
            *reinterpret_cast<float2*>(out + pbase + 256) = vv;
        } else {
            // c0: per-pixel soft VQ on x
            units = 64u;
            float is = s_is;
            float bsc = sbs[bc % 3];
            #pragma unroll
            for (int r = 0; r < 2; r++) {
                float2 xv = *reinterpret_cast<const float2*>(g_x + pbase + r*256);
                int i0, i1;
                float v0 = vq8(fmaf(xv.x, is, bsc), sc, i0);
                float v1 = vq8(fmaf(xv.y, is, bsc), sc, i1);
                hcnt += (1u << (i0*4)) + (1u << (i1*4));
                *reinterpret_cast<float2*>(out + pbase + r*256) = make_float2(v0, v1);
            }
        }
    }

    // ---- warp reductions (full warps; no divergence here) ----
    unsigned int wsum = __reduce_add_sync(0xffffffffu, units);
    if ((tid & 31) == 0) atomicAdd(&sesti, wsum);
    #pragma unroll
    for (int k = 0; k < 8; k++) {
        unsigned int c = (hcnt >> (4*k)) & 0xFu;
        unsigned int w = __reduce_add_sync(0xffffffffu, c);
        if ((tid & 31) == 0 && w) atomicAdd(&shist[k], w);
    }
    __syncthreads();
    if (tid < 8) {
        if (shist[tid]) atomicAdd(&g_counts[tid], shist[tid]);
        if (tid == 0) atomicAdd(&g_esti16, sesti);
        __threadfence();
    }
    __syncthreads();

    if (tid == 0) {
        unsigned int ticket = atomicAdd(&g_done, 1u);
        if (ticket == gridDim.x - 1) {
            double tot = 0.0;
            double c[8];
            for (int k = 0; k < 8; k++) {
                c[k] = (double)atomicAdd(&g_counts[k], 0u);
                tot += c[k];
            }
            double mean = 0.0;
            for (int k = 0; k < 8; k++) { c[k] /= tot; mean += c[k]; }
            mean /= 8.0;
            double var = 0.0;
            for (int k = 0; k < 8; k++) { double d = c[k] - mean; var += d*d; }
            double stdv = sqrt(var / 7.0);
            double esti = (double)atomicAdd(&g_esti16, 0u) / 16.0;
            double cr = (1.0/16.0) * esti / (256.0*256.0*3.0*8.0);
            out[soft_n]     = (float)cr;
            out[soft_n + 1] = (float)stdv;
            for (int k = 0; k < 8; k++) g_counts[k] = 0u;
            g_esti16 = 0u;
            __threadfence();
            atomicExch(&g_done, 0u);
        }
    }
}

// ---------------- launch ----------------
extern "C" void kernel_launch(void* const* d_in, const int* in_sizes, int n_in,
                              void* d_out, int out_size) {
    const float* x_init   = (const float*)d_in[0];
    const float* thresh   = (const float*)d_in[1];
    const float* sample_w = (const float*)d_in[2];
    const float* sample_b = (const float*)d_in[3];
    const float* centers  = (const float*)d_in[4];
    const float* pool1_w  = (const float*)d_in[5];
    const float* pool1_b  = (const float*)d_in[6];
    const float* pool2_w  = (const float*)d_in[7];
    const float* pool2_b  = (const float*)d_in[8];
    const float* ctx_w    = (const float*)d_in[9];
    const float* ctx_b    = (const float*)d_in[10];
    const float* bng      = (const float*)d_in[11];
    const float* bnb      = (const float*)d_in[12];
    float* out = (float*)d_out;
    int soft_n = out_size - 2;

    k_fused<<<dim3(256, 8), 256>>>(x_init, sample_w,
                                   ctx_w + 0*81, ctx_b + 0*3, bng + 0*3, bnb + 0*3);
    k_ctx1pool<<<2176, 256>>>(ctx_w + 1*81, ctx_b + 1*3, bng + 1*3, bnb + 1*3,
                              sample_w, sample_b,
                              pool1_w, pool1_b, pool2_w, pool2_b);
    k_tail23<<<512, 256>>>(ctx_w + 2*81, ctx_b + 2*3, bng + 2*3, bnb + 2*3,
                           ctx_w + 3*81, ctx_b + 3*3, bng + 3*3, bnb + 3*3);
    k_mega<<<1536, 256>>>(thresh, centers, sample_b, out, soft_n);
}

// round 15
// speedup vs baseline: 1.0004x; 1.0004x over previous
#include <cuda_runtime.h>
#include <math.h>

#define NB 8
#define NC 3

// ---------------- scratch (device globals; no runtime allocation) ----------------
__device__ float g_x [NB*NC*256*256];   // UNSCALED sample conv output (no sigma, no bias)
__device__ float g_h0[NB*NC*512*512];
__device__ float g_h1[NB*NC*256*256];
__device__ float g_h2[NB*NC*128*128];
__device__ float g_h3[NB*NC*64*64];
__device__ float g_p1[NB*NC*128*128];
__device__ float g_p2[NB*NC*64*64];
__device__ float g_inv_sigma;
__device__ unsigned int g_counts[8];    // zero-init at load; reset by mega finalize
__device__ unsigned int g_esti16;
__device__ unsigned int g_done = 0;
__device__ unsigned int g_bar_cnt = 0;
__device__ unsigned int g_bar_sense = 0;

// ---------------- fused: sample conv (4x4 s4, unscaled) + ctx stage 0 ----------------
__global__ void k_fused(const float* __restrict__ x,
                        const float* __restrict__ samw,
                        const float* __restrict__ cw,
                        const float* __restrict__ cb,
                        const float* __restrict__ bng,
                        const float* __restrict__ bnb) {
    __shared__ float ssw[144];
    __shared__ float scw[81], scb[3], sinv[3], sbb[3];
    int tid = threadIdx.x;
    if (tid < 144) ssw[tid] = samw[tid];
    if (tid < 81)  scw[tid] = cw[tid];
    if (tid < 3) {
        scb[tid]  = cb[tid];
        sinv[tid] = bng[tid] * rsqrtf(1.001f);
        sbb[tid]  = bnb[tid];
    }
    __syncthreads();

    int ox = threadIdx.x;
    int oy = blockIdx.x;
    int b  = blockIdx.y;

    float as0 = 0.f, as1 = 0.f, as2 = 0.f;
    float ac[2][2][3];
    #pragma unroll
    for (int sy = 0; sy < 2; sy++)
        #pragma unroll
        for (int sx = 0; sx < 2; sx++)
            #pragma unroll
            for (int oc = 0; oc < 3; oc++)
                ac[sy][sx][oc] = scb[oc];

    bool left = (ox > 0);

    #pragma unroll
    for (int ic = 0; ic < 3; ic++) {
        const float* base = x + (size_t)(b*3 + ic)*1024*1024;
        float inv = sinv[ic], bb = sbb[ic];
        #pragma unroll
        for (int r5 = 0; r5 < 5; r5++) {
            int iy = 4*oy + r5 - 1;
            float u0, u1, u2, u3, u4;
            if (iy >= 0) {
                const float* rp = base + (size_t)iy*1024 + 4*ox;
                float4 v4 = *reinterpret_cast<const float4*>(rp);
                float vm = left ? rp[-1] : 0.f;
                u0 = left ? fmaxf(fmaf(inv, vm, bb), 0.f) : 0.f;
                u1 = fmaxf(fmaf(inv, v4.x, bb), 0.f);
                u2 = fmaxf(fmaf(inv, v4.y, bb), 0.f);
                u3 = fmaxf(fmaf(inv, v4.z, bb), 0.f);
                u4 = fmaxf(fmaf(inv, v4.w, bb), 0.f);
                if (r5 >= 1) {
                    int ky = r5 - 1;
                    const float* w0 = &ssw[(0*3 + ic)*16 + ky*4];
                    const float* w1 = &ssw[(1*3 + ic)*16 + ky*4];
                    const float* w2 = &ssw[(2*3 + ic)*16 + ky*4];
                    as0 += w0[0]*v4.x + w0[1]*v4.y + w0[2]*v4.z + w0[3]*v4.w;
                    as1 += w1[0]*v4.x + w1[1]*v4.y + w1[2]*v4.z + w1[3]*v4.w;
                    as2 += w2[0]*v4.x + w2[1]*v4.y + w2[2]*v4.z + w2[3]*v4.w;
                }
            } else {
                u0 = u1 = u2 = u3 = u4 = 0.f;
            }
            if (r5 <= 2) {
                #pragma unroll
                for (int oc = 0; oc < 3; oc++) {
                    const float* wp = &scw[oc*27 + ic*9 + r5*3];
                    ac[0][0][oc] = fmaf(wp[0], u0, fmaf(wp[1], u1, fmaf(wp[2], u2, ac[0][0][oc])));
                    ac[0][1][oc] = fmaf(wp[0], u2, fmaf(wp[1], u3, fmaf(wp[2], u4, ac[0][1][oc])));
                }
            }
            if (r5 >= 2) {
                int ky = r5 - 2;
                #pragma unroll
                for (int oc = 0; oc < 3; oc++) {
                    const float* wp = &scw[oc*27 + ic*9 + ky*3];
                    ac[1][0][oc] = fmaf(wp[0], u0, fmaf(wp[1], u1, fmaf(wp[2], u2, ac[1][0][oc])));
                    ac[1][1][oc] = fmaf(wp[0], u2, fmaf(wp[1], u3, fmaf(wp[2], u4, ac[1][1][oc])));
                }
            }
        }
    }

    g_x[((b*3 + 0)*256 + oy)*256 + ox] = as0;
    g_x[((b*3 + 1)*256 + oy)*256 + ox] = as1;
    g_x[((b*3 + 2)*256 + oy)*256 + ox] = as2;

    #pragma unroll
    for (int oc = 0; oc < 3; oc++) {
        #pragma unroll
        for (int sy = 0; sy < 2; sy++) {
            size_t o = ((size_t)(b*3 + oc)*512 + 2*oy + sy)*512 + 2*ox;
            *reinterpret_cast<float2*>(g_h0 + o) = make_float2(ac[sy][0][oc], ac[sy][1][oc]);
        }
    }
}

// ---------------- per-pixel ctx conv body (stages 1..3) ----------------
template<int STAGE>
__device__ __forceinline__ void ctx_px_body(int i,
                                            const float* sw, const float* sb,
                                            const float* sinv, const float* sbb) {
    constexpr int INH  = (STAGE == 1) ? 512 : (STAGE == 2) ? 256 : 128;
    constexpr int OUTW = INH / 2;
    constexpr int LOG  = (STAGE == 1) ? 8 : (STAGE == 2) ? 7 : 6;
    const float* in = (STAGE == 1) ? g_h0 : (STAGE == 2) ? g_h1 : g_h2;
    float* outp     = (STAGE == 1) ? g_h1 : (STAGE == 2) ? g_h2 : g_h3;

    int ox = i & (OUTW - 1);
    int oy = (i >> LOG) & (OUTW - 1);
    int b  = i >> (2*LOG);

    float a0 = sb[0], a1 = sb[1], a2 = sb[2];
    bool left = (ox > 0);
    #pragma unroll
    for (int ic = 0; ic < 3; ic++) {
        const float* base = in + (size_t)(b*3 + ic)*INH*INH;
        float inv = sinv[ic], bb = sbb[ic];
        #pragma unroll
        for (int r = 0; r < 3; r++) {
            int iy = 2*oy + r - 1;
            float uL = 0.f, u0 = 0.f, u1 = 0.f;
            if (iy >= 0) {
                const float* rp = base + (size_t)iy*INH + 2*ox;
                float2 v = *reinterpret_cast<const float2*>(rp);
                u0 = fmaxf(fmaf(inv, v.x, bb), 0.f);
                u1 = fmaxf(fmaf(inv, v.y, bb), 0.f);
                if (left) uL = fmaxf(fmaf(inv, rp[-1], bb), 0.f);
            }
            const float* wp = &sw[ic*9 + r*3];
            a0 = fmaf(wp[0],  uL, fmaf(wp[1],  u0, fmaf(wp[2],  u1, a0)));
            a1 = fmaf(wp[27], uL, fmaf(wp[28], u0, fmaf(wp[29], u1, a1)));
            a2 = fmaf(wp[54], uL, fmaf(wp[55], u0, fmaf(wp[56], u1, a2)));
        }
    }
    outp[((b*3 + 0)*OUTW + oy)*OUTW + ox] = a0;
    outp[((b*3 + 1)*OUTW + oy)*OUTW + ox] = a1;
    outp[((b*3 + 2)*OUTW + oy)*OUTW + ox] = a2;
}

// ---------------- role-split: ctx1 (blocks [0,2048)) + pools (blocks [2048,2176)) ----------------
__global__ void k_ctx1pool(const float* __restrict__ w1c, const float* __restrict__ b1c,
                           const float* __restrict__ bng1, const float* __restrict__ bnb1,
                           const float* __restrict__ samw, const float* __restrict__ samb,
                           const float* __restrict__ pw1, const float* __restrict__ pb1,
                           const float* __restrict__ pw2, const float* __restrict__ pb2) {
    int tid = threadIdx.x;
    if (blockIdx.x < 2048) {
        __shared__ float sw[81], sb[3], sinv[3], sbb[3];
        for (int t = tid; t < 81; t += 256) sw[t] = w1c[t];
        if (tid < 3) {
            sb[tid]   = b1c[tid];
            sinv[tid] = bng1[tid] * rsqrtf(1.001f);
            sbb[tid]  = bnb1[tid];
        }
        __syncthreads();
        int i = blockIdx.x*256 + tid;
        ctx_px_body<1>(i, sw, sb, sinv, sbb);
    } else {
        __shared__ float sG[9];
        __shared__ float sis;
        __shared__ float sw1[36], sw2[36], sb1[3], sb2[3], sbs[3];
        if (tid < 36) { sw1[tid] = pw1[tid]; sw2[tid] = pw2[tid]; }
        if (tid >= 64 && tid < 67) {
            int c = tid - 64;
            sb1[c] = pb1[c]; sb2[c] = pb2[c]; sbs[c] = samb[c];
        }
        if (tid >= 96 && tid < 105) {
            int t9 = tid - 96;
            int ii = t9 / 3, jj = t9 % 3;
            float s0 = 0.f, s1 = 0.f, s2 = 0.f, s3 = 0.f;
            #pragma unroll
            for (int k = 0; k < 48; k += 4) {
                s0 += samw[ii*48 + k + 0] * samw[jj*48 + k + 0];
                s1 += samw[ii*48 + k + 1] * samw[jj*48 + k + 1];
                s2 += samw[ii*48 + k + 2] * samw[jj*48 + k + 2];
                s3 += samw[ii*48 + k + 3] * samw[jj*48 + k + 3];
            }
            sG[t9] = (s0 + s1) + (s2 + s3);
        }
        __syncthreads();
        if (tid == 0) {
            float g00 = sG[0], g01 = sG[1], g02 = sG[2];
            float g11 = sG[4], g12 = sG[5], g22 = sG[8];
            float q  = (g00 + g11 + g22) * (1.f/3.f);
            float pp = g01*g01 + g02*g02 + g12*g12;
            float d0 = g00 - q, d1 = g11 - q, d2 = g22 - q;
            float p2 = d0*d0 + d1*d1 + d2*d2 + 2.f*pp;
            float lam;
            if (p2 <= 1e-30f) {
                lam = q;
            } else {
                float p  = sqrtf(p2 * (1.f/6.f));
                float ip = 1.f/p;
                float b00 = d0*ip, b11 = d1*ip, b22 = d2*ip;
                float b01 = g01*ip, b02 = g02*ip, b12 = g12*ip;
                float detB = b00*(b11*b22 - b12*b12)
                           - b01*(b01*b22 - b12*b02)
                           + b02*(b01*b12 - b11*b02);
                float r = fminf(1.f, fmaxf(-1.f, 0.5f*detB));
                lam = q + 2.f*p*cosf(acosf(r)*(1.f/3.f));
            }
            float is = rsqrtf(lam);
            sis = is;
            if (blockIdx.x == 2048) g_inv_sigma = is;
        }
        __syncthreads();
        float is = sis;

        int i  = (blockIdx.x - 2048)*256 + tid;
        int ox = i & 63;
        int oy = (i >> 6) & 63;
        int b  = i >> 12;

        float p1v[2][2][3];
        #pragma unroll
        for (int sy = 0; sy < 2; sy++)
            #pragma unroll
            for (int sx = 0; sx < 2; sx++)
                #pragma unroll
                for (int mc = 0; mc < 3; mc++)
                    p1v[sy][sx][mc] = sb1[mc];

        #pragma unroll
        for (int ic = 0; ic < 3; ic++) {
            const float* base = g_x + (size_t)(b*3 + ic)*65536 + (size_t)(4*oy)*256 + 4*ox;
            float bsc = sbs[ic];
            float rx[4][4];
            #pragma unroll
            for (int r = 0; r < 4; r++) {
                float4 v = *reinterpret_cast<const float4*>(base + r*256);
                rx[r][0] = fmaf(v.x, is, bsc);
                rx[r][1] = fmaf(v.y, is, bsc);
                rx[r][2] = fmaf(v.z, is, bsc);
                rx[r][3] = fmaf(v.w, is, bsc);
            }
            #pragma unroll
            for (int mc = 0; mc < 3; mc++) {
                const float* wp = &sw1[mc*12 + ic*4];
                #pragma unroll
                for (int sy = 0; sy < 2; sy++)
                    #pragma unroll
                    for (int sx = 0; sx < 2; sx++)
                        p1v[sy][sx][mc] += wp[0]*rx[2*sy][2*sx]   + wp[1]*rx[2*sy][2*sx+1]
                                         + wp[2]*rx[2*sy+1][2*sx] + wp[3]*rx[2*sy+1][2*sx+1];
            }
        }

        #pragma unroll
        for (int mc = 0; mc < 3; mc++)
            #pragma unroll
            for (int sy = 0; sy < 2; sy++) {
                size_t o = ((size_t)(b*3 + mc)*128 + 2*oy + sy)*128 + 2*ox;
                *reinterpret_cast<float2*>(g_p1 + o) = make_float2(p1v[sy][0][mc], p1v[sy][1][mc]);
            }

        #pragma unroll
        for (int oc = 0; oc < 3; oc++) {
            float a = sb2[oc];
            #pragma unroll
            for (int mc = 0; mc < 3; mc++) {
                const float* wp = &sw2[oc*12 + mc*4];
                a += wp[0]*p1v[0][0][mc] + wp[1]*p1v[0][1][mc]
                   + wp[2]*p1v[1][0][mc] + wp[3]*p1v[1][1][mc];
            }
            g_p2[((size_t)(b*3 + oc)*64 + oy)*64 + ox] = a;
        }
    }
}

// ---------------- ctx2 + ctx3 in one kernel with a co-resident grid barrier ----------------
__global__ void __launch_bounds__(256, 4)
k_tail23(const float* __restrict__ w2c, const float* __restrict__ b2c,
         const float* __restrict__ bng2, const float* __restrict__ bnb2,
         const float* __restrict__ w3c, const float* __restrict__ b3c,
         const float* __restrict__ bng3, const float* __restrict__ bnb3) {
    __shared__ float sw2[81], sb2[3], sinv2[3], sbb2[3];
    __shared__ float sw3[81], sb3[3], sinv3[3], sbb3[3];
    int tid = threadIdx.x;
    for (int t = tid; t < 81; t += 256) { sw2[t] = w2c[t]; sw3[t] = w3c[t]; }
    if (tid < 3) {
        sb2[tid]   = b2c[tid];
        sinv2[tid] = bng2[tid] * rsqrtf(1.001f);
        sbb2[tid]  = bnb2[tid];
        sb3[tid]   = b3c[tid];
        sinv3[tid] = bng3[tid] * rsqrtf(1.001f);
        sbb3[tid]  = bnb3[tid];
    }
    __syncthreads();

    int i = blockIdx.x*256 + tid;
    ctx_px_body<2>(i, sw2, sb2, sinv2, sbb2);

    __threadfence();
    __syncthreads();
    if (tid == 0) {
        unsigned int S = *(volatile unsigned int*)&g_bar_sense;
        unsigned int a = atomicAdd(&g_bar_cnt, 1u);
        if (a == gridDim.x - 1u) {
            g_bar_cnt = 0u;
            __threadfence();
            atomicExch(&g_bar_sense, S ^ 1u);
        } else {
            while (*(volatile unsigned int*)&g_bar_sense == S) { }
        }
    }
    __syncthreads();

    if (i < NB*64*64) {
        ctx_px_body<3>(i, sw3, sb3, sinv3, sbb3);
    }
}

// ---------------- soft VQ of one scalar (no side effects; returns argmin) ----------------
__device__ __forceinline__ float vq8(float x, const float* sc, int& imin) {
    float dd[8];
    float dmin = 3.4e38f;
    imin = 0;
    #pragma unroll
    for (int k = 0; k < 8; k++) {
        float d = (x - sc[k])*(x - sc[k]);
        dd[k] = d;
        if (d < dmin) { dmin = d; imin = k; }
    }
    float s = 0.f, sn = 0.f;
    #pragma unroll
    for (int k = 0; k < 8; k++) {
        float e = __expf(dmin - dd[k]);
        s += e;
        sn = fmaf(e, sc[k], sn);
    }
    return __fdividef(sn, s);
}

// ---------------- mega: one thread per quarter-res cell -> 4x4 pixel block ----------------
// R9 mapping (best measured). Histogram counts accumulated per-thread in two
// byte-packed registers (max 16/bin < 255), reduced warp-wide with 8 REDUX at
// the end -> no per-vq8 shared atomics, no divergence in the reduction.
__global__ void k_mega(const float* __restrict__ thresh,
                       const float* __restrict__ centers,
                       const float* __restrict__ samb,
                       float* __restrict__ out, int soft_n) {
    __shared__ float sc[8];
    __shared__ unsigned int shist[8];
    __shared__ unsigned int sesti;
    __shared__ float sth[2];
    __shared__ float sbs[3];
    __shared__ float s_is;
    int tid = threadIdx.x;
    if (tid < 8) { sc[tid] = centers[tid]; shist[tid] = 0u; }
    if (tid < 2) sth[tid] = thresh[tid];
    if (tid < 3) sbs[tid] = samb[tid];
    if (tid == 0) { sesti = 0u; s_is = g_inv_sigma; }
    __syncthreads();

    int t = blockIdx.x*256 + tid;           // quarter cell index, 0..98303 (grid exact)
    int qx = t & 63, qy = (t >> 6) & 63, bc = t >> 12;
    int pbase = bc*65536 + (qy*4)*256 + qx*4;

    unsigned int units;
    unsigned int hc0 = 0u, hc1 = 0u;        // byte-packed counts: bins 0-3 / 4-7

    float f2 = 0.5f*(tanhf(g_h3[t]) + 1.0f);
    if (f2 < sth[1]) {
        // c2: whole 4x4 block shares xq = p2[qi]
        int imin;
        float v = vq8(g_p2[t], sc, imin);
        if (imin < 4) hc0 += 1u << (imin*8); else hc1 += 1u << ((imin - 4)*8);
        units = 16u;
        float4 vv = make_float4(v, v, v, v);
        #pragma unroll
        for (int r = 0; r < 4; r++)
            *reinterpret_cast<float4*>(out + pbase + r*256) = vv;
    } else {
        units = 0u;
        float is = s_is;
        float bsc = sbs[bc % 3];
        #pragma unroll
        for (int hy = 0; hy < 2; hy++) {
            #pragma unroll
            for (int hx = 0; hx < 2; hx++) {
                int hi = bc*16384 + (qy*2 + hy)*128 + (qx*2 + hx);
                int hb = pbase + hy*2*256 + hx*2;
                float f1 = 0.5f*(tanhf(g_h2[hi]) + 1.0f);
                if (f1 < sth[0]) {
                    // c1: 2x2 sub-block shares xq = p1[hi]
                    int imin;
                    float v = vq8(g_p1[hi], sc, imin);
                    if (imin < 4) hc0 += 1u << (imin*8); else hc1 += 1u << ((imin - 4)*8);
                    units += 16u;
                    float2 vv = make_float2(v, v);
                    *reinterpret_cast<float2*>(out + hb)       = vv;
                    *reinterpret_cast<float2*>(out + hb + 256) = vv;
                } else {
                    // c0: per-pixel soft VQ on x
                    units += 64u;
                    #pragma unroll
                    for (int r = 0; r < 2; r++) {
                        float2 xv = *reinterpret_cast<const float2*>(g_x + hb + r*256);
                        int i0, i1;
                        float v0 = vq8(fmaf(xv.x, is, bsc), sc, i0);
                        float v1 = vq8(fmaf(xv.y, is, bsc), sc, i1);
                        if (i0 < 4) hc0 += 1u << (i0*8); else hc1 += 1u << ((i0 - 4)*8);
                        if (i1 < 4) hc0 += 1u << (i1*8); else hc1 += 1u << ((i1 - 4)*8);
                        *reinterpret_cast<float2*>(out + hb + r*256) = make_float2(v0, v1);
                    }
                }
            }
        }
    }

    // ---- warp reductions (full warps; uniform control flow) ----
    unsigned int wsum = __reduce_add_sync(0xffffffffu, units);
    if ((tid & 31) == 0) atomicAdd(&sesti, wsum);
    #pragma unroll
    for (int k = 0; k < 4; k++) {
        unsigned int c = (hc0 >> (8*k)) & 0xFFu;
        unsigned int w = __reduce_add_sync(0xffffffffu, c);
        if ((tid & 31) == 0 && w) atomicAdd(&shist[k], w);
    }
    #pragma unroll
    for (int k = 0; k < 4; k++) {
        unsigned int c = (hc1 >> (8*k)) & 0xFFu;
        unsigned int w = __reduce_add_sync(0xffffffffu, c);
        if ((tid & 31) == 0 && w) atomicAdd(&shist[4 + k], w);
    }
    __syncthreads();
    if (tid < 8) {
        if (shist[tid]) atomicAdd(&g_counts[tid], shist[tid]);
        if (tid == 0) atomicAdd(&g_esti16, sesti);
        __threadfence();
    }
    __syncthreads();

    if (tid == 0) {
        unsigned int ticket = atomicAdd(&g_done, 1u);
        if (ticket == gridDim.x - 1) {
            double tot = 0.0;
            double c[8];
            for (int k = 0; k < 8; k++) {
                c[k] = (double)atomicAdd(&g_counts[k], 0u);
                tot += c[k];
            }
            double mean = 0.0;
            for (int k = 0; k < 8; k++) { c[k] /= tot; mean += c[k]; }
            mean /= 8.0;
            double var = 0.0;
            for (int k = 0; k < 8; k++) { double d = c[k] - mean; var += d*d; }
            double stdv = sqrt(var / 7.0);
            double esti = (double)atomicAdd(&g_esti16, 0u) / 16.0;
            double cr = (1.0/16.0) * esti / (256.0*256.0*3.0*8.0);
            out[soft_n]     = (float)cr;
            out[soft_n + 1] = (float)stdv;
            for (int k = 0; k < 8; k++) g_counts[k] = 0u;
            g_esti16 = 0u;
            __threadfence();
            atomicExch(&g_done, 0u);
        }
    }
}

// ---------------- launch ----------------
extern "C" void kernel_launch(void* const* d_in, const int* in_sizes, int n_in,
                              void* d_out, int out_size) {
    const float* x_init   = (const float*)d_in[0];
    const float* thresh   = (const float*)d_in[1];
    const float* sample_w = (const float*)d_in[2];
    const float* sample_b = (const float*)d_in[3];
    const float* centers  = (const float*)d_in[4];
    const float* pool1_w  = (const float*)d_in[5];
    const float* pool1_b  = (const float*)d_in[6];
    const float* pool2_w  = (const float*)d_in[7];
    const float* pool2_b  = (const float*)d_in[8];
    const float* ctx_w    = (const float*)d_in[9];
    const float* ctx_b    = (const float*)d_in[10];
    const float* bng      = (const float*)d_in[11];
    const float* bnb      = (const float*)d_in[12];
    float* out = (float*)d_out;
    int soft_n = out_size - 2;

    k_fused<<<dim3(256, 8), 256>>>(x_init, sample_w,
                                   ctx_w + 0*81, ctx_b + 0*3, bng + 0*3, bnb + 0*3);
    k_ctx1pool<<<2176, 256>>>(ctx_w + 1*81, ctx_b + 1*3, bng + 1*3, bnb + 1*3,
                              sample_w, sample_b,
                              pool1_w, pool1_b, pool2_w, pool2_b);
    k_tail23<<<512, 256>>>(ctx_w + 2*81, ctx_b + 2*3, bng + 2*3, bnb + 2*3,
                           ctx_w + 3*81, ctx_b + 3*3, bng + 3*3, bnb + 3*3);
    k_mega<<<384, 256>>>(thresh, centers, sample_b, out, soft_n);
}

// round 16
// speedup vs baseline: 1.0236x; 1.0232x over previous
#include <cuda_runtime.h>
#include <math.h>

#define NB 8
#define NC 3

// ---------------- scratch (device globals; no runtime allocation) ----------------
__device__ float g_x [NB*NC*256*256];   // UNSCALED sample conv output (no sigma, no bias)
__device__ float g_h0[NB*NC*512*512];
__device__ float g_h1[NB*NC*256*256];
__device__ float g_h2[NB*NC*128*128];
__device__ float g_h3[NB*NC*64*64];
__device__ float g_p1[NB*NC*128*128];
__device__ float g_p2[NB*NC*64*64];
__device__ float g_inv_sigma;
__device__ unsigned int g_counts[8];    // zero-init at load; reset by finalize
__device__ unsigned int g_esti16;
__device__ unsigned int g_done = 0;
__device__ unsigned int g_bar_cnt = 0;
__device__ unsigned int g_bar_sense = 0;

// ---------------- fused: sample conv (4x4 s4, unscaled) + ctx stage 0 ----------------
__global__ void k_fused(const float* __restrict__ x,
                        const float* __restrict__ samw,
                        const float* __restrict__ cw,
                        const float* __restrict__ cb,
                        const float* __restrict__ bng,
                        const float* __restrict__ bnb) {
    __shared__ float ssw[144];
    __shared__ float scw[81], scb[3], sinv[3], sbb[3];
    int tid = threadIdx.x;
    if (tid < 144) ssw[tid] = samw[tid];
    if (tid < 81)  scw[tid] = cw[tid];
    if (tid < 3) {
        scb[tid]  = cb[tid];
        sinv[tid] = bng[tid] * rsqrtf(1.001f);
        sbb[tid]  = bnb[tid];
    }
    __syncthreads();

    int ox = threadIdx.x;
    int oy = blockIdx.x;
    int b  = blockIdx.y;

    float as0 = 0.f, as1 = 0.f, as2 = 0.f;
    float ac[2][2][3];
    #pragma unroll
    for (int sy = 0; sy < 2; sy++)
        #pragma unroll
        for (int sx = 0; sx < 2; sx++)
            #pragma unroll
            for (int oc = 0; oc < 3; oc++)
                ac[sy][sx][oc] = scb[oc];

    bool left = (ox > 0);

    #pragma unroll
    for (int ic = 0; ic < 3; ic++) {
        const float* base = x + (size_t)(b*3 + ic)*1024*1024;
        float inv = sinv[ic], bb = sbb[ic];
        #pragma unroll
        for (int r5 = 0; r5 < 5; r5++) {
            int iy = 4*oy + r5 - 1;
            float u0, u1, u2, u3, u4;
            if (iy >= 0) {
                const float* rp = base + (size_t)iy*1024 + 4*ox;
                float4 v4 = *reinterpret_cast<const float4*>(rp);
                float vm = left ? rp[-1] : 0.f;
                u0 = left ? fmaxf(fmaf(inv, vm, bb), 0.f) : 0.f;
                u1 = fmaxf(fmaf(inv, v4.x, bb), 0.f);
                u2 = fmaxf(fmaf(inv, v4.y, bb), 0.f);
                u3 = fmaxf(fmaf(inv, v4.z, bb), 0.f);
                u4 = fmaxf(fmaf(inv, v4.w, bb), 0.f);
                if (r5 >= 1) {
                    int ky = r5 - 1;
                    const float* w0 = &ssw[(0*3 + ic)*16 + ky*4];
                    const float* w1 = &ssw[(1*3 + ic)*16 + ky*4];
                    const float* w2 = &ssw[(2*3 + ic)*16 + ky*4];
                    as0 += w0[0]*v4.x + w0[1]*v4.y + w0[2]*v4.z + w0[3]*v4.w;
                    as1 += w1[0]*v4.x + w1[1]*v4.y + w1[2]*v4.z + w1[3]*v4.w;
                    as2 += w2[0]*v4.x + w2[1]*v4.y + w2[2]*v4.z + w2[3]*v4.w;
                }
            } else {
                u0 = u1 = u2 = u3 = u4 = 0.f;
            }
            if (r5 <= 2) {
                #pragma unroll
                for (int oc = 0; oc < 3; oc++) {
                    const float* wp = &scw[oc*27 + ic*9 + r5*3];
                    ac[0][0][oc] = fmaf(wp[0], u0, fmaf(wp[1], u1, fmaf(wp[2], u2, ac[0][0][oc])));
                    ac[0][1][oc] = fmaf(wp[0], u2, fmaf(wp[1], u3, fmaf(wp[2], u4, ac[0][1][oc])));
                }
            }
            if (r5 >= 2) {
                int ky = r5 - 2;
                #pragma unroll
                for (int oc = 0; oc < 3; oc++) {
                    const float* wp = &scw[oc*27 + ic*9 + ky*3];
                    ac[1][0][oc] = fmaf(wp[0], u0, fmaf(wp[1], u1, fmaf(wp[2], u2, ac[1][0][oc])));
                    ac[1][1][oc] = fmaf(wp[0], u2, fmaf(wp[1], u3, fmaf(wp[2], u4, ac[1][1][oc])));
                }
            }
        }
    }

    g_x[((b*3 + 0)*256 + oy)*256 + ox] = as0;
    g_x[((b*3 + 1)*256 + oy)*256 + ox] = as1;
    g_x[((b*3 + 2)*256 + oy)*256 + ox] = as2;

    #pragma unroll
    for (int oc = 0; oc < 3; oc++) {
        #pragma unroll
        for (int sy = 0; sy < 2; sy++) {
            size_t o = ((size_t)(b*3 + oc)*512 + 2*oy + sy)*512 + 2*ox;
            *reinterpret_cast<float2*>(g_h0 + o) = make_float2(ac[sy][0][oc], ac[sy][1][oc]);
        }
    }
}

// ---------------- per-pixel ctx conv body (stages 1..3) ----------------
template<int STAGE>
__device__ __forceinline__ void ctx_px_body(int i,
                                            const float* sw, const float* sb,
                                            const float* sinv, const float* sbb) {
    constexpr int INH  = (STAGE == 1) ? 512 : (STAGE == 2) ? 256 : 128;
    constexpr int OUTW = INH / 2;
    constexpr int LOG  = (STAGE == 1) ? 8 : (STAGE == 2) ? 7 : 6;
    const float* in = (STAGE == 1) ? g_h0 : (STAGE == 2) ? g_h1 : g_h2;
    float* outp     = (STAGE == 1) ? g_h1 : (STAGE == 2) ? g_h2 : g_h3;

    int ox = i & (OUTW - 1);
    int oy = (i >> LOG) & (OUTW - 1);
    int b  = i >> (2*LOG);

    float a0 = sb[0], a1 = sb[1], a2 = sb[2];
    bool left = (ox > 0);
    #pragma unroll
    for (int ic = 0; ic < 3; ic++) {
        const float* base = in + (size_t)(b*3 + ic)*INH*INH;
        float inv = sinv[ic], bb = sbb[ic];
        #pragma unroll
        for (int r = 0; r < 3; r++) {
            int iy = 2*oy + r - 1;
            float uL = 0.f, u0 = 0.f, u1 = 0.f;
            if (iy >= 0) {
                const float* rp = base + (size_t)iy*INH + 2*ox;
                float2 v = *reinterpret_cast<const float2*>(rp);
                u0 = fmaxf(fmaf(inv, v.x, bb), 0.f);
                u1 = fmaxf(fmaf(inv, v.y, bb), 0.f);
                if (left) uL = fmaxf(fmaf(inv, rp[-1], bb), 0.f);
            }
            const float* wp = &sw[ic*9 + r*3];
            a0 = fmaf(wp[0],  uL, fmaf(wp[1],  u0, fmaf(wp[2],  u1, a0)));
            a1 = fmaf(wp[27], uL, fmaf(wp[28], u0, fmaf(wp[29], u1, a1)));
            a2 = fmaf(wp[54], uL, fmaf(wp[55], u0, fmaf(wp[56], u1, a2)));
        }
    }
    outp[((b*3 + 0)*OUTW + oy)*OUTW + ox] = a0;
    outp[((b*3 + 1)*OUTW + oy)*OUTW + ox] = a1;
    outp[((b*3 + 2)*OUTW + oy)*OUTW + ox] = a2;
}

// ---------------- role-split: ctx1 (blocks [0,2048)) + pools (blocks [2048,2176)) ----------------
__global__ void k_ctx1pool(const float* __restrict__ w1c, const float* __restrict__ b1c,
                           const float* __restrict__ bng1, const float* __restrict__ bnb1,
                           const float* __restrict__ samw, const float* __restrict__ samb,
                           const float* __restrict__ pw1, const float* __restrict__ pb1,
                           const float* __restrict__ pw2, const float* __restrict__ pb2) {
    int tid = threadIdx.x;
    if (blockIdx.x < 2048) {
        __shared__ float sw[81], sb[3], sinv[3], sbb[3];
        for (int t = tid; t < 81; t += 256) sw[t] = w1c[t];
        if (tid < 3) {
            sb[tid]   = b1c[tid];
            sinv[tid] = bng1[tid] * rsqrtf(1.001f);
            sbb[tid]  = bnb1[tid];
        }
        __syncthreads();
        int i = blockIdx.x*256 + tid;
        ctx_px_body<1>(i, sw, sb, sinv, sbb);
    } else {
        __shared__ float sG[9];
        __shared__ float sis;
        __shared__ float sw1[36], sw2[36], sb1[3], sb2[3], sbs[3];
        if (tid < 36) { sw1[tid] = pw1[tid]; sw2[tid] = pw2[tid]; }
        if (tid >= 64 && tid < 67) {
            int c = tid - 64;
            sb1[c] = pb1[c]; sb2[c] = pb2[c]; sbs[c] = samb[c];
        }
        if (tid >= 96 && tid < 105) {
            int t9 = tid - 96;
            int ii = t9 / 3, jj = t9 % 3;
            float s0 = 0.f, s1 = 0.f, s2 = 0.f, s3 = 0.f;
            #pragma unroll
            for (int k = 0; k < 48; k += 4) {
                s0 += samw[ii*48 + k + 0] * samw[jj*48 + k + 0];
                s1 += samw[ii*48 + k + 1] * samw[jj*48 + k + 1];
                s2 += samw[ii*48 + k + 2] * samw[jj*48 + k + 2];
                s3 += samw[ii*48 + k + 3] * samw[jj*48 + k + 3];
            }
            sG[t9] = (s0 + s1) + (s2 + s3);
        }
        __syncthreads();
        if (tid == 0) {
            float g00 = sG[0], g01 = sG[1], g02 = sG[2];
            float g11 = sG[4], g12 = sG[5], g22 = sG[8];
            float q  = (g00 + g11 + g22) * (1.f/3.f);
            float pp = g01*g01 + g02*g02 + g12*g12;
            float d0 = g00 - q, d1 = g11 - q, d2 = g22 - q;
            float p2 = d0*d0 + d1*d1 + d2*d2 + 2.f*pp;
            float lam;
            if (p2 <= 1e-30f) {
                lam = q;
            } else {
                float p  = sqrtf(p2 * (1.f/6.f));
                float ip = 1.f/p;
                float b00 = d0*ip, b11 = d1*ip, b22 = d2*ip;
                float b01 = g01*ip, b02 = g02*ip, b12 = g12*ip;
                float detB = b00*(b11*b22 - b12*b12)
                           - b01*(b01*b22 - b12*b02)
                           + b02*(b01*b12 - b11*b02);
                float r = fminf(1.f, fmaxf(-1.f, 0.5f*detB));
                lam = q + 2.f*p*cosf(acosf(r)*(1.f/3.f));
            }
            float is = rsqrtf(lam);
            sis = is;
            if (blockIdx.x == 2048) g_inv_sigma = is;
        }
        __syncthreads();
        float is = sis;

        int i  = (blockIdx.x - 2048)*256 + tid;
        int ox = i & 63;
        int oy = (i >> 6) & 63;
        int b  = i >> 12;

        float p1v[2][2][3];
        #pragma unroll
        for (int sy = 0; sy < 2; sy++)
            #pragma unroll
            for (int sx = 0; sx < 2; sx++)
                #pragma unroll
                for (int mc = 0; mc < 3; mc++)
                    p1v[sy][sx][mc] = sb1[mc];

        #pragma unroll
        for (int ic = 0; ic < 3; ic++) {
            const float* base = g_x + (size_t)(b*3 + ic)*65536 + (size_t)(4*oy)*256 + 4*ox;
            float bsc = sbs[ic];
            float rx[4][4];
            #pragma unroll
            for (int r = 0; r < 4; r++) {
                float4 v = *reinterpret_cast<const float4*>(base + r*256);
                rx[r][0] = fmaf(v.x, is, bsc);
                rx[r][1] = fmaf(v.y, is, bsc);
                rx[r][2] = fmaf(v.z, is, bsc);
                rx[r][3] = fmaf(v.w, is, bsc);
            }
            #pragma unroll
            for (int mc = 0; mc < 3; mc++) {
                const float* wp = &sw1[mc*12 + ic*4];
                #pragma unroll
                for (int sy = 0; sy < 2; sy++)
                    #pragma unroll
                    for (int sx = 0; sx < 2; sx++)
                        p1v[sy][sx][mc] += wp[0]*rx[2*sy][2*sx]   + wp[1]*rx[2*sy][2*sx+1]
                                         + wp[2]*rx[2*sy+1][2*sx] + wp[3]*rx[2*sy+1][2*sx+1];
            }
        }

        #pragma unroll
        for (int mc = 0; mc < 3; mc++)
            #pragma unroll
            for (int sy = 0; sy < 2; sy++) {
                size_t o = ((size_t)(b*3 + mc)*128 + 2*oy + sy)*128 + 2*ox;
                *reinterpret_cast<float2*>(g_p1 + o) = make_float2(p1v[sy][0][mc], p1v[sy][1][mc]);
            }

        #pragma unroll
        for (int oc = 0; oc < 3; oc++) {
            float a = sb2[oc];
            #pragma unroll
            for (int mc = 0; mc < 3; mc++) {
                const float* wp = &sw2[oc*12 + mc*4];
                a += wp[0]*p1v[0][0][mc] + wp[1]*p1v[0][1][mc]
                   + wp[2]*p1v[1][0][mc] + wp[3]*p1v[1][1][mc];
            }
            g_p2[((size_t)(b*3 + oc)*64 + oy)*64 + ox] = a;
        }
    }
}

// ---------------- grid barrier helper (sense-reversing; co-resident grids only) ----------------
__device__ __forceinline__ void grid_barrier(int tid) {
    __threadfence();
    __syncthreads();
    if (tid == 0) {
        unsigned int S = *(volatile unsigned int*)&g_bar_sense;
        unsigned int a = atomicAdd(&g_bar_cnt, 1u);
        if (a == gridDim.x - 1u) {
            g_bar_cnt = 0u;
            __threadfence();
            atomicExch(&g_bar_sense, S ^ 1u);
        } else {
            while (*(volatile unsigned int*)&g_bar_sense == S) { }
        }
    }
    __syncthreads();
}

// ---------------- soft VQ of one scalar + histogram count (R9 body) ----------------
__device__ __forceinline__ float vq8(float x, const float* sc, unsigned int* shist) {
    float dd[8];
    float dmin = 3.4e38f;
    int imin = 0;
    #pragma unroll
    for (int k = 0; k < 8; k++) {
        float d = (x - sc[k])*(x - sc[k]);
        dd[k] = d;
        if (d < dmin) { dmin = d; imin = k; }
    }
    float s = 0.f, sn = 0.f;
    #pragma unroll
    for (int k = 0; k < 8; k++) {
        float e = __expf(dmin - dd[k]);
        s += e;
        sn = fmaf(e, sc[k], sn);
    }
    atomicAdd(&shist[imin], 1u);
    return __fdividef(sn, s);
}

// ---------------- merged tail: ctx2 -> barrier -> ctx3 -> barrier -> mega+finalize ----------------
// 512 blocks x 256 thr, __launch_bounds__(256,4) -> 592 co-resident slots >= 512.
__global__ void __launch_bounds__(256, 4)
k_tailmega(const float* __restrict__ w2c, const float* __restrict__ b2c,
           const float* __restrict__ bng2, const float* __restrict__ bnb2,
           const float* __restrict__ w3c, const float* __restrict__ b3c,
           const float* __restrict__ bng3, const float* __restrict__ bnb3,
           const float* __restrict__ thresh,
           const float* __restrict__ centers,
           const float* __restrict__ samb,
           float* __restrict__ out, int soft_n) {
    __shared__ float sw2[81], sb2[3], sinv2[3], sbb2[3];
    __shared__ float sw3[81], sb3[3], sinv3[3], sbb3[3];
    __shared__ float sc[8];
    __shared__ unsigned int shist[8];
    __shared__ unsigned int sesti;
    __shared__ float sth[2];
    __shared__ float sbs[3];
    int tid = threadIdx.x;
    for (int t = tid; t < 81; t += 256) { sw2[t] = w2c[t]; sw3[t] = w3c[t]; }
    if (tid < 8) { sc[tid] = centers[tid]; shist[tid] = 0u; }
    if (tid < 2) sth[tid] = thresh[tid];
    if (tid < 3) {
        sb2[tid]   = b2c[tid];
        sinv2[tid] = bng2[tid] * rsqrtf(1.001f);
        sbb2[tid]  = bnb2[tid];
        sb3[tid]   = b3c[tid];
        sinv3[tid] = bng3[tid] * rsqrtf(1.001f);
        sbb3[tid]  = bnb3[tid];
        sbs[tid]   = samb[tid];
    }
    if (tid == 0) sesti = 0u;
    __syncthreads();

    int i = blockIdx.x*256 + tid;

    // ---- phase 1: ctx2 (exactly 512*256 = 131072 outputs) ----
    ctx_px_body<2>(i, sw2, sb2, sinv2, sbb2);

    grid_barrier(tid);

    // ---- phase 2: ctx3 (first 32768 threads) ----
    if (i < NB*64*64) {
        ctx_px_body<3>(i, sw3, sb3, sinv3, sbb3);
    }

    grid_barrier(tid);

    // ---- phase 3: mega, one thread per quarter cell (blocks [0,384) exactly) ----
    unsigned int units = 0u;
    if (blockIdx.x < 384) {
        int t = i;                          // quarter cell index, 0..98303
        int qx = t & 63, qy = (t >> 6) & 63, bc = t >> 12;
        int pbase = bc*65536 + (qy*4)*256 + qx*4;
        float is = g_inv_sigma;

        float f2 = 0.5f*(tanhf(g_h3[t]) + 1.0f);
        if (f2 < sth[1]) {
            float v = vq8(g_p2[t], sc, shist);
            units = 16u;
            float4 vv = make_float4(v, v, v, v);
            #pragma unroll
            for (int r = 0; r < 4; r++)
                *reinterpret_cast<float4*>(out + pbase + r*256) = vv;
        } else {
            float bsc = sbs[bc % 3];
            #pragma unroll
            for (int hy = 0; hy < 2; hy++) {
                #pragma unroll
                for (int hx = 0; hx < 2; hx++) {
                    int hi = bc*16384 + (qy*2 + hy)*128 + (qx*2 + hx);
                    int hb = pbase + hy*2*256 + hx*2;
                    float f1 = 0.5f*(tanhf(g_h2[hi]) + 1.0f);
                    if (f1 < sth[0]) {
                        float v = vq8(g_p1[hi], sc, shist);
                        units += 16u;
                        float2 vv = make_float2(v, v);
                        *reinterpret_cast<float2*>(out + hb)       = vv;
                        *reinterpret_cast<float2*>(out + hb + 256) = vv;
                    } else {
                        units += 64u;
                        #pragma unroll
                        for (int r = 0; r < 2; r++) {
                            float2 xv = *reinterpret_cast<const float2*>(g_x + hb + r*256);
                            float v0 = vq8(fmaf(xv.x, is, bsc), sc, shist);
                            float v1 = vq8(fmaf(xv.y, is, bsc), sc, shist);
                            *reinterpret_cast<float2*>(out + hb + r*256) = make_float2(v0, v1);
                        }
                    }
                }
            }
        }
    }

    // ---- reductions + flush (all 512 blocks participate; units=0 outside) ----
    unsigned int wsum = __reduce_add_sync(0xffffffffu, units);
    if ((tid & 31) == 0) atomicAdd(&sesti, wsum);
    __syncthreads();
    if (tid < 8) {
        if (shist[tid]) atomicAdd(&g_counts[tid], shist[tid]);
        if (tid == 0) atomicAdd(&g_esti16, sesti);
        __threadfence();
    }
    __syncthreads();

    if (tid == 0) {
        unsigned int ticket = atomicAdd(&g_done, 1u);
        if (ticket == gridDim.x - 1) {
            double tot = 0.0;
            double c[8];
            for (int k = 0; k < 8; k++) {
                c[k] = (double)atomicAdd(&g_counts[k], 0u);
                tot += c[k];
            }
            double mean = 0.0;
            for (int k = 0; k < 8; k++) { c[k] /= tot; mean += c[k]; }
            mean /= 8.0;
            double var = 0.0;
            for (int k = 0; k < 8; k++) { double d = c[k] - mean; var += d*d; }
            double stdv = sqrt(var / 7.0);
            double esti = (double)atomicAdd(&g_esti16, 0u) / 16.0;
            double cr = (1.0/16.0) * esti / (256.0*256.0*3.0*8.0);
            out[soft_n]     = (float)cr;
            out[soft_n + 1] = (float)stdv;
            for (int k = 0; k < 8; k++) g_counts[k] = 0u;
            g_esti16 = 0u;
            __threadfence();
            atomicExch(&g_done, 0u);
        }
    }
}

// ---------------- launch ----------------
extern "C" void kernel_launch(void* const* d_in, const int* in_sizes, int n_in,
                              void* d_out, int out_size) {
    const float* x_init   = (const float*)d_in[0];
    const float* thresh   = (const float*)d_in[1];
    const float* sample_w = (const float*)d_in[2];
    const float* sample_b = (const float*)d_in[3];
    const float* centers  = (const float*)d_in[4];
    const float* pool1_w  = (const float*)d_in[5];
    const float* pool1_b  = (const float*)d_in[6];
    const float* pool2_w  = (const float*)d_in[7];
    const float* pool2_b  = (const float*)d_in[8];
    const float* ctx_w    = (const float*)d_in[9];
    const float* ctx_b    = (const float*)d_in[10];
    const float* bng      = (const float*)d_in[11];
    const float* bnb      = (const float*)d_in[12];
    float* out = (float*)d_out;
    int soft_n = out_size - 2;

    k_fused<<<dim3(256, 8), 256>>>(x_init, sample_w,
                                   ctx_w + 0*81, ctx_b + 0*3, bng + 0*3, bnb + 0*3);
    k_ctx1pool<<<2176, 256>>>(ctx_w + 1*81, ctx_b + 1*3, bng + 1*3, bnb + 1*3,
                              sample_w, sample_b,
                              pool1_w, pool1_b, pool2_w, pool2_b);
    k_tailmega<<<512, 256>>>(ctx_w + 2*81, ctx_b + 2*3, bng + 2*3, bnb + 2*3,
                             ctx_w + 3*81, ctx_b + 3*3, bng + 3*3, bnb + 3*3,
                             thresh, centers, sample_b, out, soft_n);
}